// round 6
// baseline (speedup 1.0000x reference)
#include <cuda_runtime.h>
#include <cuda_fp16.h>
#include <cstdint>

#define B_ROWS   16384
#define IN_DIM   1024
#define OUT_DIM  1024
#define NGRID    9
#define GRID_LO  (-1.0f)
#define HSTEP    0.25f

#define MTILE 128
#define NTILE 128
#define BK    32
#define MAXT  136                      // 128 data tiles + <=8 padding tiles
#define STAGES 3
#define A_BYTES 8192                   // 128 rows x 64B
#define STAGE_BYTES 16384              // A + B
#define DSMEM_BYTES (STAGES * STAGE_BYTES)   // 49152

// ---------------- device scratch ----------------
__device__ __half  g_ax[(size_t)NGRID * B_ROWS * IN_DIM];    // w-scaled X, fp16
__device__ __half  g_cf[(size_t)NGRID * OUT_DIM * IN_DIM];   // coeff, fp16
__device__ int     g_pid[B_ROWS];          // pair id s (pair = {s, s+1})
__device__ float2  g_rw[B_ROWS];           // (w_s, w_{s+1})
__device__ int     g_hist[8];
__device__ int     g_cursor[8];
__device__ int     g_base[8];              // padded row-slot base per bin
__device__ int     g_perm[MAXT * MTILE];   // tile slot -> source row (-1 = pad)
__device__ int     g_tg1[MAXT];            // tile -> first segment of pair
__device__ int     g_tact[MAXT];           // tile active flag
__device__ int     g_gmask;

// ---------------- helpers ----------------
__device__ __forceinline__ uint32_t smem_u32(const void* p) {
    uint32_t a;
    asm("{ .reg .u64 t; cvta.to.shared.u64 t, %1; cvt.u32.u64 %0, t; }" : "=r"(a) : "l"(p));
    return a;
}
__device__ __forceinline__ void cp16(uint32_t dst, const void* src) {
    asm volatile("cp.async.cg.shared.global [%0], [%1], 16;" :: "r"(dst), "l"(src) : "memory");
}
// swizzled byte offset inside a [rows][32 halfs] tile (64B pitch)
__device__ __forceinline__ uint32_t swz(int r, int c) {
    return (uint32_t)(r * 64 + ((c ^ ((r >> 1) & 3)) << 4));
}
#define LDSM_X4(r0, r1, r2, r3, addr) \
    asm volatile("ldmatrix.sync.aligned.m8n8.x4.shared.b16 {%0,%1,%2,%3}, [%4];" \
        : "=r"(r0), "=r"(r1), "=r"(r2), "=r"(r3) : "r"(addr))
#define MMA16816(d, a, b) \
    asm volatile("mma.sync.aligned.m16n8k16.row.col.f32.f16.f16.f32 " \
        "{%0,%1,%2,%3}, {%4,%5,%6,%7}, {%8,%9}, {%0,%1,%2,%3};" \
        : "+f"((d)[0]), "+f"((d)[1]), "+f"((d)[2]), "+f"((d)[3]) \
        : "r"((a)[0]), "r"((a)[1]), "r"((a)[2]), "r"((a)[3]), "r"((b)[0]), "r"((b)[1]))

// ---------------------------------------------------------------------------
// Kernel 1: per-row mean -> normalized hat weights -> active pair (s, s+1)
// Also resets global counters (no other kernel-1 block touches them).
// ---------------------------------------------------------------------------
__global__ void kan_weights_kernel(const float* __restrict__ x) {
    if (blockIdx.x == 0 && threadIdx.x == 0) {
        #pragma unroll
        for (int i = 0; i < 8; i++) g_hist[i] = 0;
        g_gmask = 0;
    }
    const int row = blockIdx.x;
    const float4 v = reinterpret_cast<const float4*>(x + (size_t)row * IN_DIM)[threadIdx.x];
    float s = v.x + v.y + v.z + v.w;
    #pragma unroll
    for (int o = 16; o > 0; o >>= 1) s += __shfl_xor_sync(0xFFFFFFFFu, s, o);

    __shared__ float warp_sums[8];
    if ((threadIdx.x & 31) == 0) warp_sums[threadIdx.x >> 5] = s;
    __syncthreads();

    if (threadIdx.x == 0) {
        float tot = 0.0f;
        #pragma unroll
        for (int i = 0; i < 8; i++) tot += warp_sums[i];
        const float mean = tot * (1.0f / IN_DIM);
        float w[NGRID]; float sum = 0.0f;
        #pragma unroll
        for (int g = 0; g < NGRID; g++) {
            const float gp = GRID_LO + HSTEP * (float)g;
            float t = 1.0f - fabsf(mean - gp) / HSTEP;
            t = t > 0.0f ? t : 0.0f;
            w[g] = t; sum += t;
        }
        const float inv = 1.0f / (sum + 1e-8f);
        int sg = (int)floorf((mean - GRID_LO) / HSTEP);
        sg = sg < 0 ? 0 : (sg > 7 ? 7 : sg);
        g_pid[row] = sg;
        g_rw[row] = make_float2(w[sg] * inv, w[sg + 1] * inv);
    }
}

// ---------------------------------------------------------------------------
// Kernel 2: histogram over pair ids + global segment mask
// ---------------------------------------------------------------------------
__global__ void kan_hist_kernel() {
    __shared__ int sh[8];
    __shared__ int sm;
    if (threadIdx.x < 8) sh[threadIdx.x] = 0;
    if (threadIdx.x == 0) sm = 0;
    __syncthreads();
    const int row = blockIdx.x * 256 + threadIdx.x;
    const int p = g_pid[row];
    atomicAdd(&sh[p], 1);
    atomicOr(&sm, (1 << p) | (1 << (p + 1)));
    __syncthreads();
    if (threadIdx.x < 8) atomicAdd(&g_hist[threadIdx.x], sh[threadIdx.x]);
    if (threadIdx.x == 0) atomicOr(&g_gmask, sm);
}

// ---------------------------------------------------------------------------
// Kernel 3 (1 block): prefix sums, tile table, perm init, cursor reset
// ---------------------------------------------------------------------------
__global__ void kan_plan_kernel() {
    if (threadIdx.x == 0) {
        int T = 0, base = 0;
        #pragma unroll
        for (int p = 0; p < 8; p++) {
            g_base[p] = base;
            g_cursor[p] = 0;
            const int nt = (g_hist[p] + MTILE - 1) / MTILE;
            for (int j = 0; j < nt; j++) { g_tg1[T] = p; g_tact[T] = 1; T++; }
            base += nt * MTILE;
        }
        for (; T < MAXT; T++) g_tact[T] = 0;
    }
    for (int i = threadIdx.x; i < MAXT * MTILE; i += blockDim.x) g_perm[i] = -1;
}

// ---------------------------------------------------------------------------
// Kernel 4: scatter rows into padded bins
// ---------------------------------------------------------------------------
__global__ void kan_scatter_kernel() {
    const int row = blockIdx.x * 256 + threadIdx.x;
    const int p = g_pid[row];
    const int pos = g_base[p] + atomicAdd(&g_cursor[p], 1);
    g_perm[pos] = row;
}

// ---------------------------------------------------------------------------
// Kernel 5: w-scaled X -> fp16 for the row's own two segments
// ---------------------------------------------------------------------------
__global__ void kan_scale_kernel(const float* __restrict__ x) {
    const int row = blockIdx.x;
    const int sg = g_pid[row];
    const float2 w2 = g_rw[row];
    const float4 v = reinterpret_cast<const float4*>(x + (size_t)row * IN_DIM)[threadIdx.x];
    #pragma unroll
    for (int gi = 0; gi < 2; gi++) {
        const int g = sg + gi;
        const float w = gi ? w2.y : w2.x;
        __half2 h0 = __floats2half2_rn(w * v.x, w * v.y);
        __half2 h1 = __floats2half2_rn(w * v.z, w * v.w);
        uint2 u;
        u.x = *reinterpret_cast<uint32_t*>(&h0);
        u.y = *reinterpret_cast<uint32_t*>(&h1);
        *reinterpret_cast<uint2*>(&g_ax[((size_t)g << 24) + ((size_t)row << 10) + threadIdx.x * 4]) = u;
    }
}

// ---------------------------------------------------------------------------
// Kernel 6: coeff fp32 -> fp16, only segments used by some row
// ---------------------------------------------------------------------------
__global__ void kan_cvt_coeff_kernel(const float* __restrict__ coeff) {
    const int g = blockIdx.x >> 9;            // 512 blocks per segment
    if (!((g_gmask >> g) & 1)) return;
    const size_t base = ((size_t)blockIdx.x * 256 + threadIdx.x) * 8;
    const float4 a = *reinterpret_cast<const float4*>(coeff + base);
    const float4 b = *reinterpret_cast<const float4*>(coeff + base + 4);
    __half2 h0 = __floats2half2_rn(a.x, a.y);
    __half2 h1 = __floats2half2_rn(a.z, a.w);
    __half2 h2 = __floats2half2_rn(b.x, b.y);
    __half2 h3 = __floats2half2_rn(b.z, b.w);
    uint4 u;
    u.x = *reinterpret_cast<uint32_t*>(&h0);
    u.y = *reinterpret_cast<uint32_t*>(&h1);
    u.z = *reinterpret_cast<uint32_t*>(&h2);
    u.w = *reinterpret_cast<uint32_t*>(&h3);
    *reinterpret_cast<uint4*>(&g_cf[base]) = u;
}

// ---------------------------------------------------------------------------
// Kernel 7: HMMA GEMM over permuted pair-homogeneous tiles, concat-K (2 segs).
// CTA 128x128, BK=32, 3-stage cp.async pipeline, 8 warps (2M x 4N), warp 64x32.
// ---------------------------------------------------------------------------
__global__ void __launch_bounds__(256, 2)
kan_hmma_kernel(const float* __restrict__ bias, float* __restrict__ out) {
    extern __shared__ unsigned char dyn_smem[];
    __shared__ int s_list[2];
    __shared__ int s_perm[MTILE];
    __shared__ int s_act;

    const int tid  = threadIdx.x;
    const int wid  = tid >> 5;
    const int lane = tid & 31;
    const int wm = wid >> 2;          // 0..1 -> M offset wm*64
    const int wn = wid & 3;           // 0..3 -> N offset wn*32
    const int t  = blockIdx.y;
    const int n0 = blockIdx.x * NTILE;
    const uint32_t dynb = smem_u32(dyn_smem);

    if (tid == 0) {
        s_act = g_tact[t];
        const int g1 = g_tg1[t];
        s_list[0] = g1; s_list[1] = g1 + 1;
    }
    if (tid < MTILE) s_perm[tid] = g_perm[t * MTILE + tid];
    __syncthreads();
    if (!s_act) return;

    const int total = 2 * (IN_DIM / BK);   // 64

    float acc[4][4][4];
    #pragma unroll
    for (int mi = 0; mi < 4; mi++)
        #pragma unroll
        for (int ni = 0; ni < 4; ni++)
            #pragma unroll
            for (int e = 0; e < 4; e++) acc[mi][ni][e] = 0.0f;

    // Per-thread load coordinates: 2 consecutive 16B chunks of A and of B.
    const int lr = tid >> 1;            // row 0..127
    const int lc = (tid & 1) * 2;       // chunk 0 or 2
    int arow = s_perm[lr];
    if (arow < 0) arow = 0;             // pad rows: harmless data, never stored

    // ---- prologue ----
    #pragma unroll
    for (int s = 0; s < STAGES - 1; s++) {
        {
            const int g  = s_list[s >> 5];
            const int kb = (s & 31) * BK;
            const uint32_t sa = dynb + s * STAGE_BYTES;
            const __half* ap = g_ax + ((size_t)g << 24) + ((size_t)arow << 10) + kb + lc * 8;
            const __half* bp = g_cf + ((size_t)g << 20) + ((size_t)(n0 + lr) << 10) + kb + lc * 8;
            cp16(sa + swz(lr, lc),               ap);
            cp16(sa + swz(lr, lc + 1),           ap + 8);
            cp16(sa + A_BYTES + swz(lr, lc),     bp);
            cp16(sa + A_BYTES + swz(lr, lc + 1), bp + 8);
        }
        asm volatile("cp.async.commit_group;" ::: "memory");
    }

    // ---- main loop ----
    for (int it = 0; it < total; it++) {
        asm volatile("cp.async.wait_group %0;" :: "n"(STAGES - 2));
        __syncthreads();

        const int nxt = it + STAGES - 1;
        if (nxt < total) {
            const int g  = s_list[nxt >> 5];
            const int kb = (nxt & 31) * BK;
            const uint32_t sa = dynb + (nxt % STAGES) * STAGE_BYTES;
            const __half* ap = g_ax + ((size_t)g << 24) + ((size_t)arow << 10) + kb + lc * 8;
            const __half* bp = g_cf + ((size_t)g << 20) + ((size_t)(n0 + lr) << 10) + kb + lc * 8;
            cp16(sa + swz(lr, lc),               ap);
            cp16(sa + swz(lr, lc + 1),           ap + 8);
            cp16(sa + A_BYTES + swz(lr, lc),     bp);
            cp16(sa + A_BYTES + swz(lr, lc + 1), bp + 8);
        }
        asm volatile("cp.async.commit_group;" ::: "memory");

        const uint32_t aBase = dynb + (it % STAGES) * STAGE_BYTES;
        const uint32_t bBase = aBase + A_BYTES;

        #pragma unroll
        for (int h = 0; h < 2; h++) {
            uint32_t a[4][4], b[4][2];
            #pragma unroll
            for (int mi = 0; mi < 4; mi++) {
                const int r = wm * 64 + mi * 16 + (lane & 15);
                const int c = 2 * h + (lane >> 4);
                LDSM_X4(a[mi][0], a[mi][1], a[mi][2], a[mi][3], aBase + swz(r, c));
            }
            #pragma unroll
            for (int nj = 0; nj < 2; nj++) {
                const int r = wn * 32 + nj * 16 + ((lane & 16) >> 1) + (lane & 7);
                const int c = 2 * h + ((lane >> 3) & 1);
                LDSM_X4(b[2 * nj][0], b[2 * nj][1], b[2 * nj + 1][0], b[2 * nj + 1][1],
                        bBase + swz(r, c));
            }
            #pragma unroll
            for (int mi = 0; mi < 4; mi++)
                #pragma unroll
                for (int ni = 0; ni < 4; ni++)
                    MMA16816(acc[mi][ni], a[mi], b[ni]);
        }
    }

    // ---- epilogue: add bias, scatter-store via perm ----
    #pragma unroll
    for (int mi = 0; mi < 4; mi++) {
        const int rt0 = wm * 64 + mi * 16 + (lane >> 2);
        const int pr0 = s_perm[rt0];
        const int pr1 = s_perm[rt0 + 8];
        #pragma unroll
        for (int ni = 0; ni < 4; ni++) {
            const int col = n0 + wn * 32 + ni * 8 + 2 * (lane & 3);
            const float2 bb = *reinterpret_cast<const float2*>(bias + col);
            if (pr0 >= 0) {
                float2 o;
                o.x = acc[mi][ni][0] + bb.x;
                o.y = acc[mi][ni][1] + bb.y;
                *reinterpret_cast<float2*>(&out[(size_t)pr0 * OUT_DIM + col]) = o;
            }
            if (pr1 >= 0) {
                float2 o;
                o.x = acc[mi][ni][2] + bb.x;
                o.y = acc[mi][ni][3] + bb.y;
                *reinterpret_cast<float2*>(&out[(size_t)pr1 * OUT_DIM + col]) = o;
            }
        }
    }
}

// ---------------------------------------------------------------------------
// Launch
// ---------------------------------------------------------------------------
extern "C" void kernel_launch(void* const* d_in, const int* in_sizes, int n_in,
                              void* d_out, int out_size) {
    const float* x     = (const float*)d_in[0];   // (8,2048,1024) fp32
    const float* coeff = (const float*)d_in[1];   // (9,1024,1024) fp32
    const float* bias  = (const float*)d_in[2];   // (1024,)       fp32
    float* out = (float*)d_out;                   // (16384,1024)  fp32

    cudaFuncSetAttribute(kan_hmma_kernel,
                         cudaFuncAttributeMaxDynamicSharedMemorySize, DSMEM_BYTES);

    kan_weights_kernel<<<B_ROWS, 256>>>(x);
    kan_hist_kernel<<<B_ROWS / 256, 256>>>();
    kan_plan_kernel<<<1, 256>>>();
    kan_scatter_kernel<<<B_ROWS / 256, 256>>>();
    kan_scale_kernel<<<B_ROWS, 256>>>(x);
    kan_cvt_coeff_kernel<<<NGRID * 512, 256>>>(coeff);

    dim3 grid(OUT_DIM / NTILE, MAXT);   // (8, 136)
    kan_hmma_kernel<<<grid, 256, DSMEM_BYTES>>>(bias, out);
}

// round 7
// speedup vs baseline: 1.7429x; 1.7429x over previous
#include <cuda_runtime.h>
#include <cuda_fp16.h>
#include <cstdint>

#define B_ROWS   16384
#define IN_DIM   1024
#define OUT_DIM  1024
#define NGRID    9
#define GRID_LO  (-1.0f)
#define HSTEP    0.25f

#define MTILE 128
#define NTILE 128
#define BK    32
#define KCAT  2048                     // concat-K: 2 segments x 1024
#define MAXT  136                      // <=128 data tiles + <=8 padding tiles
#define STAGES 3
#define A_BYTES 8192                   // 128 rows x 64B
#define STAGE_BYTES 16384              // A + B
#define DSMEM_BYTES (STAGES * STAGE_BYTES)   // 49152

// ---------------- device scratch ----------------
__device__ __half  g_axp[(size_t)MAXT * MTILE * KCAT];       // packed w-scaled X (70MB)
__device__ __half  g_cfp[(size_t)8 * OUT_DIM * KCAT];        // packed pair coeff (32MB)
__device__ int     g_pid[B_ROWS];          // pair id s (pair = {s, s+1})
__device__ float2  g_rw[B_ROWS];           // (w_s, w_{s+1})
__device__ int     g_slot[B_ROWS];         // row -> packed slot
__device__ int     g_hist[8];
__device__ int     g_cursor[8];
__device__ int     g_base[8];              // padded row-slot base per bin
__device__ int     g_perm[MAXT * MTILE];   // slot -> source row (-1 = pad)
__device__ int     g_tpair[MAXT];          // tile -> pair id
__device__ int     g_tact[MAXT];
__device__ int     g_pmask;

// ---------------- helpers ----------------
__device__ __forceinline__ uint32_t smem_u32(const void* p) {
    uint32_t a;
    asm("{ .reg .u64 t; cvta.to.shared.u64 t, %1; cvt.u32.u64 %0, t; }" : "=r"(a) : "l"(p));
    return a;
}
__device__ __forceinline__ void cp16(uint32_t dst, const void* src) {
    asm volatile("cp.async.cg.shared.global [%0], [%1], 16;" :: "r"(dst), "l"(src) : "memory");
}
// swizzled byte offset inside a [rows][32 halfs] tile (64B pitch)
__device__ __forceinline__ uint32_t swz(int r, int c) {
    return (uint32_t)(r * 64 + ((c ^ ((r >> 1) & 3)) << 4));
}
#define LDSM_X4(r0, r1, r2, r3, addr) \
    asm volatile("ldmatrix.sync.aligned.m8n8.x4.shared.b16 {%0,%1,%2,%3}, [%4];" \
        : "=r"(r0), "=r"(r1), "=r"(r2), "=r"(r3) : "r"(addr))
#define MMA16816(d, a, b) \
    asm volatile("mma.sync.aligned.m16n8k16.row.col.f32.f16.f16.f32 " \
        "{%0,%1,%2,%3}, {%4,%5,%6,%7}, {%8,%9}, {%0,%1,%2,%3};" \
        : "+f"((d)[0]), "+f"((d)[1]), "+f"((d)[2]), "+f"((d)[3]) \
        : "r"((a)[0]), "r"((a)[1]), "r"((a)[2]), "r"((a)[3]), "r"((b)[0]), "r"((b)[1]))

// ---------------------------------------------------------------------------
// Kernel 1: per-row mean -> pair id + 2 normalized hat weights; reset counters
// ---------------------------------------------------------------------------
__global__ void kan_weights_kernel(const float* __restrict__ x) {
    if (blockIdx.x == 0 && threadIdx.x == 0) {
        #pragma unroll
        for (int i = 0; i < 8; i++) g_hist[i] = 0;
    }
    const int row = blockIdx.x;
    const float4 v = reinterpret_cast<const float4*>(x + (size_t)row * IN_DIM)[threadIdx.x];
    float s = v.x + v.y + v.z + v.w;
    #pragma unroll
    for (int o = 16; o > 0; o >>= 1) s += __shfl_xor_sync(0xFFFFFFFFu, s, o);

    __shared__ float warp_sums[8];
    if ((threadIdx.x & 31) == 0) warp_sums[threadIdx.x >> 5] = s;
    __syncthreads();

    if (threadIdx.x == 0) {
        float tot = 0.0f;
        #pragma unroll
        for (int i = 0; i < 8; i++) tot += warp_sums[i];
        const float mean = tot * (1.0f / IN_DIM);
        float w[NGRID]; float sum = 0.0f;
        #pragma unroll
        for (int g = 0; g < NGRID; g++) {
            const float gp = GRID_LO + HSTEP * (float)g;
            float t = 1.0f - fabsf(mean - gp) / HSTEP;
            t = t > 0.0f ? t : 0.0f;
            w[g] = t; sum += t;
        }
        const float inv = 1.0f / (sum + 1e-8f);
        int sg = (int)floorf((mean - GRID_LO) / HSTEP);
        sg = sg < 0 ? 0 : (sg > 7 ? 7 : sg);
        g_pid[row] = sg;
        g_rw[row] = make_float2(w[sg] * inv, w[sg + 1] * inv);
    }
}

// ---------------------------------------------------------------------------
// Kernel 2: histogram over pair ids (block-aggregated)
// ---------------------------------------------------------------------------
__global__ void kan_hist_kernel() {
    __shared__ int sh[8];
    if (threadIdx.x < 8) sh[threadIdx.x] = 0;
    __syncthreads();
    const int row = blockIdx.x * 256 + threadIdx.x;
    atomicAdd(&sh[g_pid[row]], 1);
    __syncthreads();
    if (threadIdx.x < 8) atomicAdd(&g_hist[threadIdx.x], sh[threadIdx.x]);
}

// ---------------------------------------------------------------------------
// Kernel 3 (1 block): tile table, bases, cursors, perm init, pair mask
// ---------------------------------------------------------------------------
__global__ void kan_plan_kernel() {
    if (threadIdx.x == 0) {
        int T = 0, base = 0, pm = 0;
        #pragma unroll
        for (int p = 0; p < 8; p++) {
            g_base[p] = base;
            g_cursor[p] = 0;
            const int h = g_hist[p];
            if (h > 0) pm |= (1 << p);
            const int nt = (h + MTILE - 1) / MTILE;
            for (int j = 0; j < nt; j++) { g_tpair[T] = p; g_tact[T] = 1; T++; }
            base += nt * MTILE;
        }
        for (; T < MAXT; T++) g_tact[T] = 0;
        g_pmask = pm;
    }
    for (int i = threadIdx.x; i < MAXT * MTILE; i += blockDim.x) g_perm[i] = -1;
}

// ---------------------------------------------------------------------------
// Kernel 4: scatter rows into padded bins (block-aggregated atomics)
// ---------------------------------------------------------------------------
__global__ void kan_scatter_kernel() {
    __shared__ int cnt[8], basei[8];
    const int tid = threadIdx.x;
    const int row = blockIdx.x * 256 + tid;
    if (tid < 8) cnt[tid] = 0;
    __syncthreads();
    const int p = g_pid[row];
    const int lrank = atomicAdd(&cnt[p], 1);
    __syncthreads();
    if (tid < 8) basei[tid] = atomicAdd(&g_cursor[tid], cnt[tid]);
    __syncthreads();
    const int pos = g_base[p] + basei[p] + lrank;
    g_perm[pos] = row;
    g_slot[row] = pos;
}

// ---------------------------------------------------------------------------
// Kernel 5: w-scaled X -> fp16 packed at the row's slot (concat-K, 2 segs)
// ---------------------------------------------------------------------------
__global__ void kan_scale_kernel(const float* __restrict__ x) {
    const int row = blockIdx.x;
    const int slot = g_slot[row];
    const float2 w2 = g_rw[row];
    const float4 v = reinterpret_cast<const float4*>(x + (size_t)row * IN_DIM)[threadIdx.x];
    __half* dst = g_axp + (size_t)slot * KCAT + threadIdx.x * 4;
    #pragma unroll
    for (int gi = 0; gi < 2; gi++) {
        const float w = gi ? w2.y : w2.x;
        __half2 h0 = __floats2half2_rn(w * v.x, w * v.y);
        __half2 h1 = __floats2half2_rn(w * v.z, w * v.w);
        uint2 u;
        u.x = *reinterpret_cast<uint32_t*>(&h0);
        u.y = *reinterpret_cast<uint32_t*>(&h1);
        *reinterpret_cast<uint2*>(dst + gi * IN_DIM) = u;
    }
}

// ---------------------------------------------------------------------------
// Kernel 6: coeff fp32 -> fp16 packed per active pair (concat-K)
// grid: 8 pairs x 1024 blocks; thread handles 8 contiguous k2
// ---------------------------------------------------------------------------
__global__ void kan_cvt_pair_kernel(const float* __restrict__ coeff) {
    const int p = blockIdx.x >> 10;
    if (!((g_pmask >> p) & 1)) return;
    const int idx = (blockIdx.x & 1023) * 256 + threadIdx.x;  // 0..262143
    const int n  = idx >> 8;           // 256 chunks of 8 per row
    const int kc = (idx & 255) * 8;    // k2 offset
    const int seg = p + (kc >> 10);
    const int k = kc & 1023;
    const float* src = coeff + (size_t)seg * (OUT_DIM * IN_DIM) + (size_t)n * IN_DIM + k;
    const float4 a = *reinterpret_cast<const float4*>(src);
    const float4 b = *reinterpret_cast<const float4*>(src + 4);
    __half2 h0 = __floats2half2_rn(a.x, a.y);
    __half2 h1 = __floats2half2_rn(a.z, a.w);
    __half2 h2 = __floats2half2_rn(b.x, b.y);
    __half2 h3 = __floats2half2_rn(b.z, b.w);
    uint4 u;
    u.x = *reinterpret_cast<uint32_t*>(&h0);
    u.y = *reinterpret_cast<uint32_t*>(&h1);
    u.z = *reinterpret_cast<uint32_t*>(&h2);
    u.w = *reinterpret_cast<uint32_t*>(&h3);
    *reinterpret_cast<uint4*>(g_cfp + (size_t)p * (OUT_DIM * KCAT) + (size_t)n * KCAT + kc) = u;
}

// ---------------------------------------------------------------------------
// Kernel 7: dense HMMA GEMM on packed tiles, K=2048, scatter epilogue.
// CTA 128x128, BK=32, 3-stage cp.async, 8 warps (2M x 4N), warp 64x32.
// ---------------------------------------------------------------------------
__global__ void __launch_bounds__(256, 2)
kan_hmma_kernel(const float* __restrict__ bias, float* __restrict__ out) {
    extern __shared__ unsigned char dyn_smem[];
    __shared__ int s_perm[MTILE];

    const int tid  = threadIdx.x;
    const int wid  = tid >> 5;
    const int lane = tid & 31;
    const int wm = wid >> 2;
    const int wn = wid & 3;
    const int t  = blockIdx.y;
    const int n0 = blockIdx.x * NTILE;
    const uint32_t dynb = smem_u32(dyn_smem);

    if (!g_tact[t]) return;
    const int pair = g_tpair[t];
    if (tid < MTILE) s_perm[tid] = g_perm[t * MTILE + tid];
    __syncthreads();

    const int total = KCAT / BK;   // 64

    float acc[4][4][4];
    #pragma unroll
    for (int mi = 0; mi < 4; mi++)
        #pragma unroll
        for (int ni = 0; ni < 4; ni++)
            #pragma unroll
            for (int e = 0; e < 4; e++) acc[mi][ni][e] = 0.0f;

    const int lr = tid >> 1;            // row 0..127
    const int lc = (tid & 1) * 2;       // chunk 0 or 2
    const __half* aRow = g_axp + ((size_t)t * MTILE + lr) * KCAT + lc * 8;
    const __half* bRow = g_cfp + (size_t)pair * (OUT_DIM * KCAT) + (size_t)(n0 + lr) * KCAT + lc * 8;

    // ---- prologue ----
    #pragma unroll
    for (int s = 0; s < STAGES - 1; s++) {
        {
            const int kb = s * BK;
            const uint32_t sa = dynb + s * STAGE_BYTES;
            cp16(sa + swz(lr, lc),               aRow + kb);
            cp16(sa + swz(lr, lc + 1),           aRow + kb + 8);
            cp16(sa + A_BYTES + swz(lr, lc),     bRow + kb);
            cp16(sa + A_BYTES + swz(lr, lc + 1), bRow + kb + 8);
        }
        asm volatile("cp.async.commit_group;" ::: "memory");
    }

    // ---- main loop ----
    for (int it = 0; it < total; it++) {
        asm volatile("cp.async.wait_group %0;" :: "n"(STAGES - 2));
        __syncthreads();

        const int nxt = it + STAGES - 1;
        if (nxt < total) {
            const int kb = nxt * BK;
            const uint32_t sa = dynb + (nxt % STAGES) * STAGE_BYTES;
            cp16(sa + swz(lr, lc),               aRow + kb);
            cp16(sa + swz(lr, lc + 1),           aRow + kb + 8);
            cp16(sa + A_BYTES + swz(lr, lc),     bRow + kb);
            cp16(sa + A_BYTES + swz(lr, lc + 1), bRow + kb + 8);
        }
        asm volatile("cp.async.commit_group;" ::: "memory");

        const uint32_t aBase = dynb + (it % STAGES) * STAGE_BYTES;
        const uint32_t bBase = aBase + A_BYTES;

        #pragma unroll
        for (int h = 0; h < 2; h++) {
            uint32_t a[4][4], b[4][2];
            #pragma unroll
            for (int mi = 0; mi < 4; mi++) {
                const int r = wm * 64 + mi * 16 + (lane & 15);
                const int c = 2 * h + (lane >> 4);
                LDSM_X4(a[mi][0], a[mi][1], a[mi][2], a[mi][3], aBase + swz(r, c));
            }
            #pragma unroll
            for (int nj = 0; nj < 2; nj++) {
                const int r = wn * 32 + nj * 16 + ((lane & 16) >> 1) + (lane & 7);
                const int c = 2 * h + ((lane >> 3) & 1);
                LDSM_X4(b[2 * nj][0], b[2 * nj][1], b[2 * nj + 1][0], b[2 * nj + 1][1],
                        bBase + swz(r, c));
            }
            #pragma unroll
            for (int mi = 0; mi < 4; mi++)
                #pragma unroll
                for (int ni = 0; ni < 4; ni++)
                    MMA16816(acc[mi][ni], a[mi], b[ni]);
        }
    }

    // ---- epilogue: add bias, scatter-store via perm ----
    #pragma unroll
    for (int mi = 0; mi < 4; mi++) {
        const int rt0 = wm * 64 + mi * 16 + (lane >> 2);
        const int pr0 = s_perm[rt0];
        const int pr1 = s_perm[rt0 + 8];
        #pragma unroll
        for (int ni = 0; ni < 4; ni++) {
            const int col = n0 + wn * 32 + ni * 8 + 2 * (lane & 3);
            const float2 bb = *reinterpret_cast<const float2*>(bias + col);
            if (pr0 >= 0) {
                float2 o;
                o.x = acc[mi][ni][0] + bb.x;
                o.y = acc[mi][ni][1] + bb.y;
                *reinterpret_cast<float2*>(&out[(size_t)pr0 * OUT_DIM + col]) = o;
            }
            if (pr1 >= 0) {
                float2 o;
                o.x = acc[mi][ni][2] + bb.x;
                o.y = acc[mi][ni][3] + bb.y;
                *reinterpret_cast<float2*>(&out[(size_t)pr1 * OUT_DIM + col]) = o;
            }
        }
    }
}

// ---------------------------------------------------------------------------
// Launch
// ---------------------------------------------------------------------------
extern "C" void kernel_launch(void* const* d_in, const int* in_sizes, int n_in,
                              void* d_out, int out_size) {
    const float* x     = (const float*)d_in[0];   // (8,2048,1024) fp32
    const float* coeff = (const float*)d_in[1];   // (9,1024,1024) fp32
    const float* bias  = (const float*)d_in[2];   // (1024,)       fp32
    float* out = (float*)d_out;                   // (16384,1024)  fp32

    cudaFuncSetAttribute(kan_hmma_kernel,
                         cudaFuncAttributeMaxDynamicSharedMemorySize, DSMEM_BYTES);

    kan_weights_kernel<<<B_ROWS, 256>>>(x);
    kan_hist_kernel<<<B_ROWS / 256, 256>>>();
    kan_plan_kernel<<<1, 256>>>();
    kan_scatter_kernel<<<B_ROWS / 256, 256>>>();
    kan_scale_kernel<<<B_ROWS, 256>>>(x);
    kan_cvt_pair_kernel<<<8 * 1024, 256>>>(coeff);

    dim3 grid(OUT_DIM / NTILE, MAXT);   // (8, 136)
    kan_hmma_kernel<<<grid, 256, DSMEM_BYTES>>>(bias, out);
}